// round 1
// baseline (speedup 1.0000x reference)
#include <cuda_runtime.h>

#define BB 4
#define CC 256
#define HH 64
#define WW 96
#define ND 21
#define CBK 8

// Block: (dy-group of 7, y, b). Threads: 252 active of 256.
//   thread -> (pxg in [0,12), dyl in [0,7), dxg in [0,3))
//   pxg -> parity p = pxg&1, group g = pxg>>1 : pixels x = 16g + 2k + p, k in [0,8)
//   thread accumulates 8 pixels x 8 dx in registers over all 256 channels.
// Parity-split smem: in2 row padded x' in [-20,115] -> per-parity arrays of 68 (+4 pad).
__global__ __launch_bounds__(256, 2)
void corr_kernel(const float* __restrict__ in1, const float* __restrict__ in2,
                 float* __restrict__ out) {
    const int dyg = blockIdx.x;      // 0..2  (dy indices 7*dyg .. 7*dyg+6)
    const int y   = blockIdx.y;      // 0..63
    const int b   = blockIdx.z;      // 0..3

    __shared__ __align__(16) float s1[CBK][2][48];
    __shared__ __align__(16) float s2[CBK][7][2][72];

    const int tid = threadIdx.x;

    // zero the pad tail (indices 68..71) of every parity row once
    for (int idx = tid; idx < CBK * 7 * 2 * 4; idx += 256) {
        int q = idx & 3;
        int rest = idx >> 2;
        int pp = rest & 1; rest >>= 1;
        int dl = rest % 7;
        int cc = rest / 7;
        s2[cc][dl][pp][68 + q] = 0.f;
    }

    const int pxg = tid % 12;
    const int dyl = (tid / 12) % 7;
    const int dxg = tid / 84;              // 0..2 active, 3 -> idle
    const bool active = (dxg < 3);
    const int g = pxg >> 1;
    const int p = pxg & 1;

    const int dyi = 7 * dyg + dyl;         // 0..20

    float acc[64];
#pragma unroll
    for (int i = 0; i < 64; i++) acc[i] = 0.f;

    for (int c0 = 0; c0 < CC; c0 += CBK) {
        __syncthreads();   // previous compute done before overwrite

        // stage 7 in2 rows (zero-padded), parity-split: s2[cc][dl][t&1][t>>1]
        for (int idx = tid; idx < CBK * 7 * 136; idx += 256) {
            int t = idx % 136;             // padded x index, x' = t - 20
            int rowi = idx / 136;
            int dl = rowi % 7;
            int cc = rowi / 7;
            int yy = y + 2 * (7 * dyg + dl) - 20;
            int x2 = t - 20;
            float v = 0.f;
            if ((unsigned)yy < (unsigned)HH && (unsigned)x2 < (unsigned)WW)
                v = in2[((b * CC + c0 + cc) * HH + yy) * WW + x2];
            s2[cc][dl][t & 1][t >> 1] = v;
        }
        // stage in1 row, parity-split
        for (int idx = tid; idx < CBK * 96; idx += 256) {
            int x = idx % 96;
            int cc = idx / 96;
            s1[cc][x & 1][x >> 1] = in1[((b * CC + c0 + cc) * HH + y) * WW + x];
        }
        __syncthreads();

        if (active) {
#pragma unroll
            for (int cc = 0; cc < CBK; cc++) {
                const float4 A0 = *(const float4*)&s1[cc][p][8 * g];
                const float4 A1 = *(const float4*)&s1[cc][p][8 * g + 4];
                const float* vp = &s2[cc][dyl][p][8 * (g + dxg)];
                const float4 V0 = *(const float4*)(vp);
                const float4 V1 = *(const float4*)(vp + 4);
                const float4 V2 = *(const float4*)(vp + 8);
                const float4 V3 = *(const float4*)(vp + 12);
                float a[8] = {A0.x, A0.y, A0.z, A0.w, A1.x, A1.y, A1.z, A1.w};
                float w[16] = {V0.x, V0.y, V0.z, V0.w, V1.x, V1.y, V1.z, V1.w,
                               V2.x, V2.y, V2.z, V2.w, V3.x, V3.y, V3.z, V3.w};
#pragma unroll
                for (int j = 0; j < 8; j++) {
#pragma unroll
                    for (int k = 0; k < 8; k++) {
                        acc[j * 8 + k] = fmaf(a[k], w[k + j], acc[j * 8 + k]);
                    }
                }
            }
        }
    }

    if (active) {
        const int ndx = (dxg == 2) ? 5 : 8;   // dx indices 8*dxg + j must stay < 21
        const float scale = 1.f / 256.f;
        for (int j = 0; j < ndx; j++) {
            int d = dyi * ND + 8 * dxg + j;   // displacement channel
            float* op = out + ((b * ND * ND + d) * HH + y) * WW + (16 * g + p);
#pragma unroll
            for (int k = 0; k < 8; k++)
                op[2 * k] = acc[j * 8 + k] * scale;
        }
    }
}

extern "C" void kernel_launch(void* const* d_in, const int* in_sizes, int n_in,
                              void* d_out, int out_size) {
    const float* in1 = (const float*)d_in[0];
    const float* in2 = (const float*)d_in[1];
    float* out = (float*)d_out;
    dim3 grid(3, HH, BB);
    corr_kernel<<<grid, 256>>>(in1, in2, out);
}

// round 2
// speedup vs baseline: 1.8249x; 1.8249x over previous
#include <cuda_runtime.h>

#define BB 4
#define CC 256
#define HH 64
#define WW 96
#define ND 21
#define CBK 4
#define NCH (CC / CBK)            // 64 chunks
#define CSTRIDE (CBK * HH * WW)   // 24576 floats between chunks

// Block: (dyg in [0,3), y, b). 256 threads.
// Compute roles: tid -> pxg=tid%12 (g=pxg>>1 in [0,6), p=pxg&1), dyl=(tid/12)%7, dxg=tid/84 (<3 active).
// Each active thread: 8 same-parity pixels x = 16g+2k+p (k<8), 8 dx = 8*dxg+j (j<8), all 256 ch.
// Staging roles (fixed): warps 0-6 stage in2 interior (float4), warp 7 stages in1.
// Parity-split smem; halo/OOB rows stay zero forever (zeroed once, never rewritten).
__global__ __launch_bounds__(256, 2)
void corr_kernel(const float* __restrict__ in1, const float* __restrict__ in2,
                 float* __restrict__ out) {
    const int dyg = blockIdx.x;
    const int y   = blockIdx.y;
    const int b   = blockIdx.z;

    __shared__ __align__(16) float s1[2][CBK][2][48];    // [buf][cc][parity][pos]
    __shared__ __align__(16) float s2[2][28][2][72];     // [buf][ri=dl*4+cc][parity][pos]

    const int tid = threadIdx.x;

    // zero both s2 buffers once (halo + OOB rows rely on this persisting)
    for (int i = tid; i < 2 * 28 * 2 * 72; i += 256)
        ((float*)s2)[i] = 0.f;

    // ---- fixed staging roles ----
    const bool is2 = (tid < 224);
    const float* gp[3];
    int   offs[3];
    bool  val[3];
    if (is2) {
#pragma unroll
        for (int j = 0; j < 3; j++) {
            int slot = j * 224 + tid;          // 0..671 covers 28 rows x 24 quads
            int row  = slot / 24;
            int q    = slot - row * 24;        // quad: covers x2 = 4q..4q+3
            int dl   = row >> 2;
            int cc   = row & 3;
            int yy   = y + 14 * dyg + 2 * dl - 20;
            val[j]  = ((unsigned)yy < (unsigned)HH);
            gp[j]   = in2 + (((size_t)b * CC + cc) * HH + yy) * WW + 4 * q;
            offs[j] = row * 144 + 2 * q + 10;  // p0 pos within one s2 buffer; p1 = +72
        }
    } else {
        int t1 = tid - 224;
#pragma unroll
        for (int j = 0; j < 3; j++) {
            int slot = j * 32 + t1;            // 0..95 covers 4 cc x 24 quads
            int cc   = slot / 24;
            int q    = slot - cc * 24;
            val[j]  = true;
            gp[j]   = in1 + (((size_t)b * CC + cc) * HH + y) * WW + 4 * q;
            offs[j] = cc * 96 + 2 * q;         // p0 pos within one s1 buffer; p1 = +48
        }
    }

    // ---- compute roles ----
    const int pxg = tid % 12;
    const int dyl = (tid / 12) % 7;
    const int dxg = tid / 84;
    const bool active = (dxg < 3);
    const int g = pxg >> 1;
    const int p = pxg & 1;
    const int dyi = 7 * dyg + dyl;

    float4 pf[3];
    auto do_ldg = [&]() {
#pragma unroll
        for (int j = 0; j < 3; j++) {
            if (val[j]) pf[j] = *(const float4*)gp[j];
            gp[j] += CSTRIDE;
        }
    };
    auto do_sts = [&](int bsel) {
        if (is2) {
            float* base = &s2[bsel][0][0][0];
#pragma unroll
            for (int j = 0; j < 3; j++) {
                if (val[j]) {
                    float2 e = make_float2(pf[j].x, pf[j].z);
                    float2 o = make_float2(pf[j].y, pf[j].w);
                    *(float2*)(base + offs[j])      = e;
                    *(float2*)(base + offs[j] + 72) = o;
                }
            }
        } else {
            float* base = &s1[bsel][0][0][0];
#pragma unroll
            for (int j = 0; j < 3; j++) {
                float2 e = make_float2(pf[j].x, pf[j].z);
                float2 o = make_float2(pf[j].y, pf[j].w);
                *(float2*)(base + offs[j])      = e;
                *(float2*)(base + offs[j] + 48) = o;
            }
        }
    };

    float acc[64];
#pragma unroll
    for (int i = 0; i < 64; i++) acc[i] = 0.f;

    // prologue: stage chunk 0 into buf 0
    do_ldg();
    do_sts(0);
    __syncthreads();

    int bb = 0;
#pragma unroll 1
    for (int k = 0; k < NCH; k++) {
        const bool pre = (k + 1 < NCH);
        if (pre) do_ldg();            // chunk k+1 -> registers (latency hidden by compute)

        if (active) {
            const float* a_base = &s1[bb][0][p][8 * g];
            const float* w_base = &s2[bb][4 * dyl][p][8 * (g + dxg)];
#pragma unroll
            for (int cc = 0; cc < CBK; cc++) {
                float4 A0 = *(const float4*)(a_base + cc * 96);
                float4 A1 = *(const float4*)(a_base + cc * 96 + 4);
                const float* wp = w_base + cc * 144;
                float4 V0 = *(const float4*)(wp);
                float4 V1 = *(const float4*)(wp + 4);
                float4 V2 = *(const float4*)(wp + 8);
                float4 V3 = *(const float4*)(wp + 12);
                float a[8] = {A0.x, A0.y, A0.z, A0.w, A1.x, A1.y, A1.z, A1.w};
                float w[16] = {V0.x, V0.y, V0.z, V0.w, V1.x, V1.y, V1.z, V1.w,
                               V2.x, V2.y, V2.z, V2.w, V3.x, V3.y, V3.z, V3.w};
#pragma unroll
                for (int j = 0; j < 8; j++)
#pragma unroll
                    for (int kk = 0; kk < 8; kk++)
                        acc[j * 8 + kk] = fmaf(a[kk], w[kk + j], acc[j * 8 + kk]);
            }
        }

        if (pre) do_sts(bb ^ 1);      // commit chunk k+1 to the other buffer
        __syncthreads();
        bb ^= 1;
    }

    if (active) {
        const int ndx = (dxg == 2) ? 5 : 8;
        const float scale = 1.f / 256.f;
        for (int j = 0; j < ndx; j++) {
            int d = dyi * ND + 8 * dxg + j;
            float* op = out + (((size_t)b * ND * ND + d) * HH + y) * WW + (16 * g + p);
#pragma unroll
            for (int kk = 0; kk < 8; kk++)
                op[2 * kk] = acc[j * 8 + kk] * scale;
        }
    }
}

extern "C" void kernel_launch(void* const* d_in, const int* in_sizes, int n_in,
                              void* d_out, int out_size) {
    const float* in1 = (const float*)d_in[0];
    const float* in2 = (const float*)d_in[1];
    float* out = (float*)d_out;
    dim3 grid(3, HH, BB);
    corr_kernel<<<grid, 256>>>(in1, in2, out);
}

// round 3
// speedup vs baseline: 3.7335x; 2.0458x over previous
#include <cuda_runtime.h>

#define BB 4
#define CC 256
#define HH 64
#define WW 96
#define ND 21
#define CBK 4
#define NCH 64
#define CSTRIDE (CBK * HH * WW)

// swizzled smem geometry (float units)
#define S1P 240     // s1 parity pitch  (240 % 32 == 16)
#define S1B 480     // s1 per-buffer floats
#define S2P 336     // s2 parity pitch  (336 % 32 == 16)
#define S2D 680     // s2 dyl pitch     (680 % 32 == 8  -> 2-chunk shift)
#define S2B 4760    // s2 per-buffer floats (7 * 680)

// Layouts (channel-transposed, slot-swizzled):
//   s1[buf][p][slot][cc] : slot = xh + (xh>>3), xh = x>>1   (A row, 48 halves)
//   s2[buf][dyl][p][slot][cc] : slot = pos + (pos>>3), pos = (x2+20)>>1 in [0,68)
// Reads: A float4 (4 ch) at slot 9g+kk ; V float4 at slot 9s+m (+1 for m>=8), s=g+dxg.
// Lane->bank map is conflict-free (2 lanes / 16B group / phase) by construction.
__global__ __launch_bounds__(256, 2)
void corr_kernel(const float* __restrict__ in1, const float* __restrict__ in2,
                 float* __restrict__ out) {
    const int dyg = blockIdx.x;   // 0..2
    const int y   = blockIdx.y;   // 0..63
    const int b   = blockIdx.z;   // 0..3

    __shared__ __align__(16) float S1[2 * S1B];
    __shared__ __align__(16) float S2[2 * S2B];

    const int tid = threadIdx.x;

    // zero everything once; gaps / OOB rows / pos>=68 pad rely on staying zero
    for (int i = tid; i < 2 * S1B; i += 256) S1[i] = 0.f;
    for (int i = tid; i < 2 * S2B; i += 256) S2[i] = 0.f;

    // ---- fixed staging roles: tids 0-223 stage in2 (672 float4), 224-255 stage in1 (96 float4)
    const bool is2 = (tid < 224);
    const float* gp[3];
    int pk[3];                    // packed: offA (parity-0 float offset) or -1 if skip
    if (is2) {
#pragma unroll
        for (int j = 0; j < 3; j++) {
            int slot = j * 224 + tid;          // 0..671
            int row  = slot / 24;              // 0..27  (dl*4 + cc)
            int q    = slot - row * 24;        // quad: x2 = 4q..4q+3
            int dl   = row >> 2;
            int cc   = row & 3;
            int yy   = y + 14 * dyg + 2 * dl - 20;
            bool v   = ((unsigned)yy < (unsigned)HH);
            gp[j]    = in2 + (((size_t)b * CC + cc) * HH + yy) * WW + 4 * q;
            int pos  = 2 * q + 10;             // parity-0 pos of x2=4q
            int sg   = pos + (pos >> 3);       // swizzled slot
            pk[j]    = v ? (dl * S2D + sg * 4 + cc) : -1;
        }
    } else {
        int t1 = tid - 224;
#pragma unroll
        for (int j = 0; j < 3; j++) {
            int slot = j * 32 + t1;            // 0..95
            int cc   = slot / 24;
            int q    = slot - cc * 24;
            gp[j]    = in1 + (((size_t)b * CC + cc) * HH + y) * WW + 4 * q;
            int pos  = 2 * q;
            int sg   = pos + (pos >> 3);
            pk[j]    = sg * 4 + cc;
        }
    }

    // ---- compute roles ----
    const int pxg = tid % 12;
    const int dyl = (tid / 12) % 7;
    const int dxg = tid / 84;                  // 0..2 active, 3 idle
    const bool active = (dxg < 3);
    const int g = pxg >> 1;
    const int p = pxg & 1;
    const int s = g + dxg;

    float4 pf[3];
    auto do_ldg = [&]() {
#pragma unroll
        for (int j = 0; j < 3; j++) {
            if (pk[j] >= 0) pf[j] = *(const float4*)gp[j];
            gp[j] += CSTRIDE;
        }
    };
    auto do_sts = [&](int bsel) {
        if (is2) {
            float* base = S2 + bsel * S2B;
#pragma unroll
            for (int j = 0; j < 3; j++) {
                if (pk[j] >= 0) {
                    base[pk[j]]           = pf[j].x;   // p0, pos
                    base[pk[j] + S2P]     = pf[j].y;   // p1, pos
                    base[pk[j] + 4]       = pf[j].z;   // p0, pos+1
                    base[pk[j] + 4 + S2P] = pf[j].w;   // p1, pos+1
                }
            }
        } else {
            float* base = S1 + bsel * S1B;
#pragma unroll
            for (int j = 0; j < 3; j++) {
                base[pk[j]]           = pf[j].x;
                base[pk[j] + S1P]     = pf[j].y;
                base[pk[j] + 4]       = pf[j].z;
                base[pk[j] + 4 + S1P] = pf[j].w;
            }
        }
    };

    float acc[64];
#pragma unroll
    for (int i = 0; i < 64; i++) acc[i] = 0.f;

    __syncthreads();              // zeroing complete before any STS (round-2 race fix)
    do_ldg();
    do_sts(0);
    __syncthreads();

#pragma unroll 1
    for (int k = 0; k < NCH; k++) {
        const bool pre = (k + 1 < NCH);
        if (pre) do_ldg();

        if (active) {
            const float4* Ab = (const float4*)(S1 + (k & 1) * S1B + p * S1P) + 9 * g;
            const float4* Vb = (const float4*)(S2 + (k & 1) * S2B + dyl * S2D + p * S2P) + 9 * s;

            float4 A[8];
#pragma unroll
            for (int kk = 0; kk < 8; kk++) A[kk] = Ab[kk];

#pragma unroll
            for (int m = 0; m < 16; m++) {
                float4 V = Vb[(m < 8) ? m : (m + 1)];
                const int klo = (m > 7) ? (m - 7) : 0;
                const int khi = (m < 7) ? m : 7;
#pragma unroll
                for (int kk = klo; kk <= khi; kk++) {
                    const int j = m - kk;
                    float t = acc[j * 8 + kk];
                    t = fmaf(A[kk].x, V.x, t);
                    t = fmaf(A[kk].y, V.y, t);
                    t = fmaf(A[kk].z, V.z, t);
                    t = fmaf(A[kk].w, V.w, t);
                    acc[j * 8 + kk] = t;
                }
            }
        }

        if (pre) do_sts((k & 1) ^ 1);
        __syncthreads();
    }

    if (active) {
        const int ndx = (dxg == 2) ? 5 : 8;
        const float scale = 1.f / 256.f;
        const int dyi = 7 * dyg + dyl;
        for (int j = 0; j < ndx; j++) {
            int di = dyi * ND + 8 * dxg + j;
            float* op = out + (((size_t)b * ND * ND + di) * HH + y) * WW + (16 * g + p);
#pragma unroll
            for (int kk = 0; kk < 8; kk++)
                op[2 * kk] = acc[j * 8 + kk] * scale;
        }
    }
}

extern "C" void kernel_launch(void* const* d_in, const int* in_sizes, int n_in,
                              void* d_out, int out_size) {
    const float* in1 = (const float*)d_in[0];
    const float* in2 = (const float*)d_in[1];
    float* out = (float*)d_out;
    dim3 grid(3, HH, BB);
    corr_kernel<<<grid, 256>>>(in1, in2, out);
}